// round 1
// baseline (speedup 1.0000x reference)
#include <cuda_runtime.h>
#include <cstdint>

#define D_DIM 256
#define BM 128
#define BN 128
#define BK 32
#define PADM 4   // BM+PADM = 132 floats per smem row

// -------- scratch (no allocations allowed) --------
__device__ float g_esq[8192];
__device__ int   g_counts[8192];
__device__ int   g_bestidx[65536];
__device__ float g_partials[8192];

// -------- packed f32x2 helpers --------
static __device__ __forceinline__ unsigned long long pack2(float lo, float hi) {
    unsigned long long r;
    asm("mov.b64 %0, {%1, %2};" : "=l"(r) : "f"(lo), "f"(hi));
    return r;
}
static __device__ __forceinline__ void unpack2(unsigned long long v, float& lo, float& hi) {
    asm("mov.b64 {%0, %1}, %2;" : "=f"(lo), "=f"(hi) : "l"(v));
}
static __device__ __forceinline__ unsigned long long fma2(unsigned long long a,
                                                          unsigned long long b,
                                                          unsigned long long c) {
    unsigned long long r;
    asm("fma.rn.f32x2 %0, %1, %2, %3;" : "=l"(r) : "l"(a), "l"(b), "l"(c));
    return r;
}

// -------- kernel 1: |E_k|^2 and zero histogram --------
__global__ void prep_kernel(const float* __restrict__ E, int K) {
    int k = blockIdx.x;
    if (k >= K) return;
    const float* row = E + (size_t)k * D_DIM;
    float s = 0.f;
    for (int d = threadIdx.x; d < D_DIM; d += 64) {
        float v = row[d];
        s += v * v;
    }
    __shared__ float sh[2];
    for (int o = 16; o > 0; o >>= 1) s += __shfl_down_sync(0xffffffffu, s, o);
    if ((threadIdx.x & 31) == 0) sh[threadIdx.x >> 5] = s;
    __syncthreads();
    if (threadIdx.x == 0) {
        g_esq[k] = sh[0] + sh[1];
        g_counts[k] = 0;
    }
}

// -------- kernel 2: fused distance-GEMM + argmin --------
// score[n,k] = |E_k|^2 - 2 * z_n . E_k   (argmin-equivalent to full d2)
__global__ __launch_bounds__(256, 2)
void argmin_kernel(const float* __restrict__ Z, const float* __restrict__ E,
                   float* __restrict__ out_idx_f, int N, int K) {
    __shared__ float As[BK][BM + PADM];
    __shared__ float Bs[BK][BN + PADM];
    __shared__ float esq_s[BN];
    __shared__ float bestV[BM];
    __shared__ int   bestI[BM];

    // candidate-reduction overlay reuses the As region (dead between stages)
    float* candV = &As[0][0];                 // 128*16 floats
    int*   candI = (int*)(&As[0][0] + 2048);  // 128*16 ints  (fits: As = 4224 floats)

    const int tid = threadIdx.x;
    const int tx = tid & 15;        // code group 0..15
    const int ty = tid >> 4;        // token group 0..15
    const int m0 = blockIdx.x * BM;

    if (tid < BM) { bestV[tid] = 3.4e38f; bestI[tid] = 0; }

    const int nKC = K / BN;
    for (int kc = 0; kc < nKC; ++kc) {
        const int n0 = kc * BN;

        unsigned long long acc[8][4];
#pragma unroll
        for (int i = 0; i < 8; i++)
#pragma unroll
            for (int j = 0; j < 4; j++) acc[i][j] = 0ULL;

        if (tid < BN) esq_s[tid] = g_esq[n0 + tid];

        for (int dc = 0; dc < D_DIM; dc += BK) {
            __syncthreads();  // previous-stage reads / candidate reduce complete
#pragma unroll
            for (int p = 0; p < 4; p++) {
                int f = p * 1024 + tid * 4;
                int r = f >> 5;
                int c = f & 31;
                float4 vz = *reinterpret_cast<const float4*>(Z + (size_t)(m0 + r) * D_DIM + dc + c);
                As[c + 0][r] = vz.x; As[c + 1][r] = vz.y;
                As[c + 2][r] = vz.z; As[c + 3][r] = vz.w;
                float4 ve = *reinterpret_cast<const float4*>(E + (size_t)(n0 + r) * D_DIM + dc + c);
                Bs[c + 0][r] = ve.x; Bs[c + 1][r] = ve.y;
                Bs[c + 2][r] = ve.z; Bs[c + 3][r] = ve.w;
            }
            __syncthreads();
#pragma unroll
            for (int kk = 0; kk < BK; kk++) {
                float4 a0 = *reinterpret_cast<const float4*>(&As[kk][ty * 8]);
                float4 a1 = *reinterpret_cast<const float4*>(&As[kk][ty * 8 + 4]);
                float4 b0 = *reinterpret_cast<const float4*>(&Bs[kk][tx * 8]);
                float4 b1 = *reinterpret_cast<const float4*>(&Bs[kk][tx * 8 + 4]);
                unsigned long long B2[4];
                B2[0] = pack2(b0.x, b0.y);
                B2[1] = pack2(b0.z, b0.w);
                B2[2] = pack2(b1.x, b1.y);
                B2[3] = pack2(b1.z, b1.w);
                float av[8] = {a0.x, a0.y, a0.z, a0.w, a1.x, a1.y, a1.z, a1.w};
#pragma unroll
                for (int i = 0; i < 8; i++) {
                    unsigned long long A2 = pack2(av[i], av[i]);
#pragma unroll
                    for (int j = 0; j < 4; j++) acc[i][j] = fma2(A2, B2[j], acc[i][j]);
                }
            }
        }
        __syncthreads();  // everyone done reading tiles -> overlay is safe

        // local argmin over this thread's 8 codes, per token row (ascending code order)
#pragma unroll
        for (int i = 0; i < 8; i++) {
            float lv = 3.4e38f;
            int   li = 0;
#pragma unroll
            for (int j = 0; j < 4; j++) {
                float d0, d1;
                unpack2(acc[i][j], d0, d1);
                int c0 = tx * 8 + 2 * j;
                float v0 = esq_s[c0]     - 2.0f * d0;
                float v1 = esq_s[c0 + 1] - 2.0f * d1;
                if (v0 < lv) { lv = v0; li = c0; }
                if (v1 < lv) { lv = v1; li = c0 + 1; }
            }
            candV[(ty * 8 + i) * 16 + tx] = lv;
            candI[(ty * 8 + i) * 16 + tx] = n0 + li;
        }
        __syncthreads();

        if (tid < BM) {
            float bv = bestV[tid];
            int   bi = bestI[tid];
#pragma unroll
            for (int t = 0; t < 16; t++) {
                float v  = candV[tid * 16 + t];
                int   ii = candI[tid * 16 + t];
                if (v < bv || (v == bv && ii < bi)) { bv = v; bi = ii; }
            }
            bestV[tid] = bv;
            bestI[tid] = bi;
        }
        // next-iteration leading __syncthreads() protects candV/candI before overwrite
    }
    __syncthreads();
    if (tid < BM) {
        int n = m0 + tid;
        g_bestidx[n] = bestI[tid];
        out_idx_f[n] = (float)bestI[tid];
    }
}

// -------- kernel 3: gather z_q, commitment partials, histogram --------
__global__ void gather_kernel(const float* __restrict__ Z, const float* __restrict__ E,
                              float* __restrict__ zq_out, int N) {
    int warp = threadIdx.x >> 5;
    int lane = threadIdx.x & 31;
    int n = blockIdx.x * 8 + warp;

    float s = 0.f;
    if (n < N) {
        int idx = g_bestidx[n];
        const float* e = E + (size_t)idx * D_DIM;
        const float* z = Z + (size_t)n * D_DIM;
        float* o = zq_out + (size_t)n * D_DIM;
#pragma unroll
        for (int h = 0; h < 2; h++) {
            int off = h * 128 + lane * 4;
            float4 ev = *reinterpret_cast<const float4*>(e + off);
            float4 zv = *reinterpret_cast<const float4*>(z + off);
            float dx = ev.x - zv.x, dy = ev.y - zv.y;
            float dz = ev.z - zv.z, dw = ev.w - zv.w;
            s += dx * dx + dy * dy + dz * dz + dw * dw;
            *reinterpret_cast<float4*>(o + off) = ev;
        }
        if (lane == 0) atomicAdd(&g_counts[idx], 1);
    }
    for (int o2 = 16; o2 > 0; o2 >>= 1) s += __shfl_down_sync(0xffffffffu, s, o2);
    __shared__ float sh[8];
    if (lane == 0) sh[warp] = s;
    __syncthreads();
    if (threadIdx.x == 0) {
        float t = 0.f;
        for (int w = 0; w < 8; w++) t += sh[w];
        g_partials[blockIdx.x] = t;
    }
}

// -------- kernel 4: finalize scalars --------
__global__ void finalize_kernel(float* __restrict__ out_scalars, int N, int K, int nPart) {
    __shared__ float sh[1024];
    float s = 0.f;
    for (int i = threadIdx.x; i < nPart; i += 1024) s += g_partials[i];
    sh[threadIdx.x] = s;
    __syncthreads();
    for (int st = 512; st > 0; st >>= 1) {
        if (threadIdx.x < st) sh[threadIdx.x] += sh[threadIdx.x + st];
        __syncthreads();
    }
    float loss = 0.1f * sh[0] / (float)((size_t)N * D_DIM);
    __syncthreads();

    float e = 0.f;
    for (int i = threadIdx.x; i < K; i += 1024) {
        float p = (float)g_counts[i] / (float)N;
        e += p * logf(p + 1e-10f);
    }
    sh[threadIdx.x] = e;
    __syncthreads();
    for (int st = 512; st > 0; st >>= 1) {
        if (threadIdx.x < st) sh[threadIdx.x] += sh[threadIdx.x + st];
        __syncthreads();
    }
    if (threadIdx.x == 0) {
        out_scalars[0] = loss;
        out_scalars[1] = expf(-sh[0]);
    }
}

extern "C" void kernel_launch(void* const* d_in, const int* in_sizes, int n_in,
                              void* d_out, int out_size) {
    const float* Z = (const float*)d_in[0];       // z_e [N, 256]
    const float* E = (const float*)d_in[1];       // embeddings [K, 256]
    int N = in_sizes[0] / D_DIM;
    int K = in_sizes[1] / D_DIM;

    float* out  = (float*)d_out;
    float* zq   = out;                              // [N*256]
    float* idxf = out + (size_t)N * D_DIM;          // [N]
    float* scal = idxf + N;                         // [2]: loss, perplexity

    prep_kernel<<<K, 64>>>(E, K);
    argmin_kernel<<<N / BM, 256>>>(Z, E, idxf, N, K);
    gather_kernel<<<N / 8, 256>>>(Z, E, zq, N);
    finalize_kernel<<<1, 1024>>>(scal, N, K, N / 8);
}

// round 3
// speedup vs baseline: 2.6387x; 2.6387x over previous
#include <cuda_runtime.h>
#include <cuda_bf16.h>
#include <cstdint>

#define D_DIM 256
#define NTOK  65536
#define KCODE 4096

// ---------------- scratch globals ----------------
__device__ float g_esq[4096];
__device__ int   g_counts[4096];
__device__ float g_partials[8192];
__device__ __align__(16) __nv_bfloat16 g_Eh[4096 * 256];
__device__ float g_topv[NTOK * 4];
__device__ int   g_topi[NTOK * 4];

// SMEM layout for approx kernel
#define SM_A    0         // 128 x 256 bf16, 512B rows, swizzled = 64KB
#define SM_B0   65536
#define SM_B1   131072
#define SM_TOP  196608    // vals 128*2*4*4 = 4KB, idx 4KB
#define SM_TOPI 200704
#define SMEM_TOTAL 204800

static __device__ __forceinline__ uint32_t smem_u32(const void* p) {
    uint32_t a;
    asm("{ .reg .u64 t; cvta.to.shared.u64 t, %1; cvt.u32.u64 %0, t; }" : "=r"(a) : "l"(p));
    return a;
}
static __device__ __forceinline__ void ldsm4(uint32_t* r, uint32_t addr) {
    asm volatile("ldmatrix.sync.aligned.m8n8.x4.shared.b16 {%0,%1,%2,%3}, [%4];"
                 : "=r"(r[0]), "=r"(r[1]), "=r"(r[2]), "=r"(r[3]) : "r"(addr));
}
static __device__ __forceinline__ void mma16816(float* c, const uint32_t* a, uint32_t b0, uint32_t b1) {
    asm volatile("mma.sync.aligned.m16n8k16.row.col.f32.bf16.bf16.f32 "
                 "{%0,%1,%2,%3}, {%4,%5,%6,%7}, {%8,%9}, {%0,%1,%2,%3};"
                 : "+f"(c[0]), "+f"(c[1]), "+f"(c[2]), "+f"(c[3])
                 : "r"(a[0]), "r"(a[1]), "r"(a[2]), "r"(a[3]), "r"(b0), "r"(b1));
}
static __device__ __forceinline__ void cpasync16(uint32_t sa, const void* ga) {
    asm volatile("cp.async.cg.shared.global [%0], [%1], 16;" :: "r"(sa), "l"(ga));
}

// ordered insert into ascending top-4 (tie-break: lower index)
static __device__ __forceinline__ void ins4(float v, int i, float* tv, int* ti) {
    if (v < tv[3] || (v == tv[3] && i < ti[3])) {
        tv[3] = v; ti[3] = i;
#pragma unroll
        for (int j = 3; j > 0; j--) {
            bool sw = tv[j] < tv[j - 1] || (tv[j] == tv[j - 1] && ti[j] < ti[j - 1]);
            float fv = sw ? tv[j] : tv[j - 1];
            float gv = sw ? tv[j - 1] : tv[j];
            int   fi = sw ? ti[j] : ti[j - 1];
            int   gi = sw ? ti[j - 1] : ti[j];
            tv[j - 1] = fv; tv[j] = gv; ti[j - 1] = fi; ti[j] = gi;
        }
    }
}

// ---------------- kernel 1: prep (Eh bf16, esq, zero counts) ----------------
__global__ void prep_kernel(const float* __restrict__ E) {
    int k = blockIdx.x;
    const float* row = E + (size_t)k * D_DIM;
    float s = 0.f;
    for (int d = threadIdx.x; d < D_DIM; d += 64) {
        float v = row[d];
        s += v * v;
        g_Eh[(size_t)k * D_DIM + d] = __float2bfloat16_rn(v);
    }
    __shared__ float sh[2];
    for (int o = 16; o > 0; o >>= 1) s += __shfl_down_sync(0xffffffffu, s, o);
    if ((threadIdx.x & 31) == 0) sh[threadIdx.x >> 5] = s;
    __syncthreads();
    if (threadIdx.x == 0) { g_esq[k] = sh[0] + sh[1]; g_counts[k] = 0; }
}

// ---------------- kernel 2: bf16 mma GEMM + fused top-4 ----------------
static __device__ __forceinline__ void load_b_tile(uint32_t dst, int n0, int tid) {
    const char* gbase = (const char*)(g_Eh + (size_t)n0 * D_DIM);
#pragma unroll
    for (int i = 0; i < 16; i++) {
        int c = tid + i * 256;        // 16B-chunk id, 0..4095
        int row = c >> 5, ch = c & 31;
        uint32_t sa = dst + row * 512 + (uint32_t)((ch ^ (row & 7)) << 4);
        cpasync16(sa, gbase + row * 512 + ch * 16);
    }
}

__global__ __launch_bounds__(256, 1)
void approx_kernel(const float* __restrict__ Z) {
    extern __shared__ char smem[];
    const uint32_t sb = smem_u32(smem);
    const int tid = threadIdx.x;
    const int lane = tid & 31;
    const int wid = tid >> 5;
    const int wm = wid & 3;      // M warp index (rows wm*32)
    const int wn = wid >> 2;     // N warp index (cols wn*64)
    const int m0 = blockIdx.x * 128;

    // prologue: prefetch B tiles 0,1
    load_b_tile(sb + SM_B0, 0, tid);
    asm volatile("cp.async.commit_group;" ::: "memory");
    load_b_tile(sb + SM_B1, 128, tid);
    asm volatile("cp.async.commit_group;" ::: "memory");

    // A tile load + convert to bf16 swizzled smem
    {
        int row = tid >> 1, half = tid & 1;
        const float* zr = Z + (size_t)(m0 + row) * D_DIM;
#pragma unroll
        for (int j = 0; j < 16; j++) {
            int ch = half * 16 + j;
            float4 u = *reinterpret_cast<const float4*>(zr + ch * 8);
            float4 w = *reinterpret_cast<const float4*>(zr + ch * 8 + 4);
            __nv_bfloat162 p0 = __float22bfloat162_rn(make_float2(u.x, u.y));
            __nv_bfloat162 p1 = __float22bfloat162_rn(make_float2(u.z, u.w));
            __nv_bfloat162 p2 = __float22bfloat162_rn(make_float2(w.x, w.y));
            __nv_bfloat162 p3 = __float22bfloat162_rn(make_float2(w.z, w.w));
            uint4 pk;
            pk.x = *(uint32_t*)&p0; pk.y = *(uint32_t*)&p1;
            pk.z = *(uint32_t*)&p2; pk.w = *(uint32_t*)&p3;
            *reinterpret_cast<uint4*>(smem + SM_A + row * 512 + ((ch ^ (row & 7)) << 4)) = pk;
        }
    }

    float tv[4][4]; int ti[4][4];
#pragma unroll
    for (int s = 0; s < 4; s++)
#pragma unroll
        for (int j = 0; j < 4; j++) { tv[s][j] = 3.4e38f; ti[s][j] = 0x7FFFFFFF; }

    for (int nt = 0; nt < 32; nt++) {
        if (nt < 31) asm volatile("cp.async.wait_group 1;" ::: "memory");
        else         asm volatile("cp.async.wait_group 0;" ::: "memory");
        __syncthreads();
        const uint32_t Bb = sb + ((nt & 1) ? SM_B1 : SM_B0);

        float acc[2][8][4];
#pragma unroll
        for (int mi = 0; mi < 2; mi++)
#pragma unroll
            for (int nj = 0; nj < 8; nj++)
#pragma unroll
                for (int r = 0; r < 4; r++) acc[mi][nj][r] = 0.f;

#pragma unroll
        for (int ks = 0; ks < 16; ks++) {
            uint32_t a[2][4], b[4][4];
#pragma unroll
            for (int mi = 0; mi < 2; mi++) {
                int ar = wm * 32 + mi * 16 + (lane & 15);
                int ch = ks * 2 + (lane >> 4);
                ldsm4(a[mi], sb + SM_A + ar * 512 + ((ch ^ (ar & 7)) << 4));
            }
#pragma unroll
            for (int g = 0; g < 4; g++) {
                int br = wn * 64 + g * 16 + (lane & 7) + ((lane >> 4) & 1) * 8;
                int ch = ks * 2 + ((lane >> 3) & 1);
                ldsm4(b[g], Bb + br * 512 + ((ch ^ (br & 7)) << 4));
            }
#pragma unroll
            for (int mi = 0; mi < 2; mi++)
#pragma unroll
                for (int g = 0; g < 4; g++) {
                    mma16816(acc[mi][2 * g],     a[mi], b[g][0], b[g][1]);
                    mma16816(acc[mi][2 * g + 1], a[mi], b[g][2], b[g][3]);
                }
        }

        // epilogue: v = esq[k] - 2*dot ; update per-slot top4
        const int n0 = nt * 128 + wn * 64;
#pragma unroll
        for (int nj = 0; nj < 8; nj++) {
            int kb = n0 + nj * 8 + (lane & 3) * 2;
            float e0 = __ldg(g_esq + kb);
            float e1 = __ldg(g_esq + kb + 1);
#pragma unroll
            for (int mi = 0; mi < 2; mi++)
#pragma unroll
                for (int h = 0; h < 2; h++) {
                    int s = mi * 2 + h;
                    float v0 = e0 - 2.0f * acc[mi][nj][h * 2];
                    float v1 = e1 - 2.0f * acc[mi][nj][h * 2 + 1];
                    ins4(v0, kb,     tv[s], ti[s]);
                    ins4(v1, kb + 1, tv[s], ti[s]);
                }
        }
        __syncthreads();
        if (nt + 2 < 32) {
            load_b_tile(sb + ((nt & 1) ? SM_B1 : SM_B0), (nt + 2) * 128, tid);
            asm volatile("cp.async.commit_group;" ::: "memory");
        }
    }

    // quad merge (lanes sharing a token row differ in lane&3)
#pragma unroll
    for (int off = 1; off <= 2; off <<= 1) {
#pragma unroll
        for (int s = 0; s < 4; s++) {
            float ov[4]; int oi[4];
#pragma unroll
            for (int j = 0; j < 4; j++) {
                ov[j] = __shfl_xor_sync(0xffffffffu, tv[s][j], off);
                oi[j] = __shfl_xor_sync(0xffffffffu, ti[s][j], off);
            }
#pragma unroll
            for (int j = 0; j < 4; j++) ins4(ov[j], oi[j], tv[s], ti[s]);
        }
    }

    // stash per-wn lists, then merge across wn and write global
    float* smv = reinterpret_cast<float*>(smem + SM_TOP);
    int*   smi = reinterpret_cast<int*>(smem + SM_TOPI);
    if ((lane & 3) == 0) {
#pragma unroll
        for (int s = 0; s < 4; s++) {
            int r = wm * 32 + (s >> 1) * 16 + (s & 1) * 8 + (lane >> 2);
#pragma unroll
            for (int j = 0; j < 4; j++) {
                smv[(r * 2 + wn) * 4 + j] = tv[s][j];
                smi[(r * 2 + wn) * 4 + j] = ti[s][j];
            }
        }
    }
    __syncthreads();
    if (tid < 128) {
        float fv[4]; int fi[4];
#pragma unroll
        for (int j = 0; j < 4; j++) { fv[j] = smv[(tid * 2) * 4 + j]; fi[j] = smi[(tid * 2) * 4 + j]; }
#pragma unroll
        for (int j = 0; j < 4; j++) ins4(smv[(tid * 2 + 1) * 4 + j], smi[(tid * 2 + 1) * 4 + j], fv, fi);
        size_t t4 = (size_t)(m0 + tid) * 4;
#pragma unroll
        for (int j = 0; j < 4; j++) { g_topv[t4 + j] = fv[j]; g_topi[t4 + j] = fi[j]; }
    }
}

// ---------------- kernel 3: exact rescore + gather + loss partials + histogram ----------------
__global__ void rescue_kernel(const float* __restrict__ Z, const float* __restrict__ E,
                              float* __restrict__ zq_out, float* __restrict__ out_idx_f, int N) {
    const int warp = threadIdx.x >> 5;
    const int lane = threadIdx.x & 31;
    const int token = blockIdx.x * 8 + warp;

    const float* zr = Z + (size_t)token * D_DIM;
    float4 z0 = *reinterpret_cast<const float4*>(zr + lane * 8);
    float4 z1 = *reinterpret_cast<const float4*>(zr + lane * 8 + 4);

    int ks[4]; float dots[4];
#pragma unroll
    for (int j = 0; j < 4; j++) {
        int k = g_topi[(size_t)token * 4 + j];
        ks[j] = k;
        const float* er = E + (size_t)k * D_DIM;
        float4 e0 = *reinterpret_cast<const float4*>(er + lane * 8);
        float4 e1 = *reinterpret_cast<const float4*>(er + lane * 8 + 4);
        float d = z0.x * e0.x + z0.y * e0.y + z0.z * e0.z + z0.w * e0.w
                + z1.x * e1.x + z1.y * e1.y + z1.z * e1.z + z1.w * e1.w;
        dots[j] = d;
    }
#pragma unroll
    for (int o = 16; o > 0; o >>= 1)
#pragma unroll
        for (int j = 0; j < 4; j++) dots[j] += __shfl_xor_sync(0xffffffffu, dots[j], o);

    float bv = 3.4e38f; int bk = 0x7FFFFFFF;
#pragma unroll
    for (int j = 0; j < 4; j++) {
        float v = __ldg(g_esq + ks[j]) - 2.0f * dots[j];
        if (v < bv || (v == bv && ks[j] < bk)) { bv = v; bk = ks[j]; }
    }

    // gather winner row, commitment partial, histogram
    const float* er = E + (size_t)bk * D_DIM;
    float* orow = zq_out + (size_t)token * D_DIM;
    float s = 0.f;
#pragma unroll
    for (int h = 0; h < 2; h++) {
        int off = h * 128 + lane * 4;
        float4 ev = *reinterpret_cast<const float4*>(er + off);
        float4 zv = *reinterpret_cast<const float4*>(zr + off);
        float dx = ev.x - zv.x, dy = ev.y - zv.y, dz = ev.z - zv.z, dw = ev.w - zv.w;
        s += dx * dx + dy * dy + dz * dz + dw * dw;
        *reinterpret_cast<float4*>(orow + off) = ev;
    }
    if (lane == 0) {
        atomicAdd(&g_counts[bk], 1);
        out_idx_f[token] = (float)bk;
    }
#pragma unroll
    for (int o = 16; o > 0; o >>= 1) s += __shfl_down_sync(0xffffffffu, s, o);
    __shared__ float sh[8];
    if (lane == 0) sh[warp] = s;
    __syncthreads();
    if (threadIdx.x == 0) {
        float t = 0.f;
        for (int w = 0; w < 8; w++) t += sh[w];
        g_partials[blockIdx.x] = t;
    }
}

// ---------------- kernel 4: finalize scalars ----------------
__global__ void finalize_kernel(float* __restrict__ out_scalars, int N, int K, int nPart) {
    __shared__ float sh[1024];
    float s = 0.f;
    for (int i = threadIdx.x; i < nPart; i += 1024) s += g_partials[i];
    sh[threadIdx.x] = s;
    __syncthreads();
    for (int st = 512; st > 0; st >>= 1) {
        if (threadIdx.x < st) sh[threadIdx.x] += sh[threadIdx.x + st];
        __syncthreads();
    }
    float loss = 0.1f * sh[0] / (float)((size_t)N * D_DIM);
    __syncthreads();
    float e = 0.f;
    for (int i = threadIdx.x; i < K; i += 1024) {
        float p = (float)g_counts[i] / (float)N;
        e += p * logf(p + 1e-10f);
    }
    sh[threadIdx.x] = e;
    __syncthreads();
    for (int st = 512; st > 0; st >>= 1) {
        if (threadIdx.x < st) sh[threadIdx.x] += sh[threadIdx.x + st];
        __syncthreads();
    }
    if (threadIdx.x == 0) {
        out_scalars[0] = loss;
        out_scalars[1] = expf(-sh[0]);
    }
}

extern "C" void kernel_launch(void* const* d_in, const int* in_sizes, int n_in,
                              void* d_out, int out_size) {
    const float* Z = (const float*)d_in[0];
    const float* E = (const float*)d_in[1];
    int N = in_sizes[0] / D_DIM;
    int K = in_sizes[1] / D_DIM;

    float* out  = (float*)d_out;
    float* zq   = out;
    float* idxf = out + (size_t)N * D_DIM;
    float* scal = idxf + N;

    cudaFuncSetAttribute(approx_kernel, cudaFuncAttributeMaxDynamicSharedMemorySize, SMEM_TOTAL);

    prep_kernel<<<K, 64>>>(E);
    approx_kernel<<<N / 128, 256, SMEM_TOTAL>>>(Z);
    rescue_kernel<<<N / 8, 256>>>(Z, E, zq, idxf, N);
    finalize_kernel<<<1, 1024>>>(scal, N, K, N / 8);
}

// round 4
// speedup vs baseline: 2.8415x; 1.0769x over previous
#include <cuda_runtime.h>
#include <cstdint>

#define D_DIM 256
#define NTOK  65536
#define KCODE 4096

// ---------------- scratch globals ----------------
__device__ float2 g_ec[KCODE];          // {esq + 2048, 2*se}
__device__ float  g_zs[NTOK];           // per-token scale sz
__device__ int    g_counts[KCODE];
__device__ float  g_partials[NTOK / 8];
__device__ __align__(16) int8_t g_E8[KCODE * D_DIM];
__device__ __align__(16) int8_t g_Z8[NTOK * D_DIM];
__device__ __align__(16) uint32_t g_topk[NTOK * 4];
__device__ int    g_done;

// SMEM: A 32KB | B0 32KB | B1 32KB | tops 4KB
#define SM_A    0
#define SM_B0   32768
#define SM_B1   65536
#define SM_TOP  98304
#define SMEM_TOTAL 102400

static __device__ __forceinline__ uint32_t smem_u32(const void* p) {
    uint32_t a;
    asm("{ .reg .u64 t; cvta.to.shared.u64 t, %1; cvt.u32.u64 %0, t; }" : "=r"(a) : "l"(p));
    return a;
}
static __device__ __forceinline__ void ldsm4(uint32_t* r, uint32_t addr) {
    asm volatile("ldmatrix.sync.aligned.m8n8.x4.shared.b16 {%0,%1,%2,%3}, [%4];"
                 : "=r"(r[0]), "=r"(r[1]), "=r"(r[2]), "=r"(r[3]) : "r"(addr));
}
static __device__ __forceinline__ void imma16832(int* c, const uint32_t* a, uint32_t b0, uint32_t b1) {
    asm volatile("mma.sync.aligned.m16n8k32.row.col.s32.s8.s8.s32 "
                 "{%0,%1,%2,%3}, {%4,%5,%6,%7}, {%8,%9}, {%0,%1,%2,%3};"
                 : "+r"(c[0]), "+r"(c[1]), "+r"(c[2]), "+r"(c[3])
                 : "r"(a[0]), "r"(a[1]), "r"(a[2]), "r"(a[3]), "r"(b0), "r"(b1));
}
static __device__ __forceinline__ void cpasync16(uint32_t sa, const void* ga) {
    asm volatile("cp.async.cg.shared.global [%0], [%1], 16;" :: "r"(sa), "l"(ga));
}
// branchless ordered insert of key into ascending 4-list
static __device__ __forceinline__ void ins4u(uint32_t k, uint32_t& t0, uint32_t& t1,
                                             uint32_t& t2, uint32_t& t3) {
    if (k < t3) {
        uint32_t m2 = min(t2, k);  t3 = max(t2, k);
        uint32_t m1 = min(t1, m2); t2 = max(t1, m2);
        uint32_t m0 = min(t0, m1); t1 = max(t0, m1); t0 = m0;
    }
}
static __device__ __forceinline__ int8_t q8(float v, float inv) {
    int x = __float2int_rn(v * inv);
    return (int8_t)x;
}

// ---------------- kernel 1: prep E (esq, scale, int8) ----------------
__global__ void prep_e_kernel(const float* __restrict__ E) {
    int warp = threadIdx.x >> 5, lane = threadIdx.x & 31;
    int k = blockIdx.x * 8 + warp;
    const float* row = E + (size_t)k * D_DIM;
    float4 a = *reinterpret_cast<const float4*>(row + lane * 8);
    float4 b = *reinterpret_cast<const float4*>(row + lane * 8 + 4);
    float s = a.x * a.x + a.y * a.y + a.z * a.z + a.w * a.w
            + b.x * b.x + b.y * b.y + b.z * b.z + b.w * b.w;
    float m = fmaxf(fmaxf(fmaxf(fabsf(a.x), fabsf(a.y)), fmaxf(fabsf(a.z), fabsf(a.w))),
                    fmaxf(fmaxf(fabsf(b.x), fabsf(b.y)), fmaxf(fabsf(b.z), fabsf(b.w))));
#pragma unroll
    for (int o = 16; o > 0; o >>= 1) {
        s += __shfl_xor_sync(0xffffffffu, s, o);
        m = fmaxf(m, __shfl_xor_sync(0xffffffffu, m, o));
    }
    float inv = (m > 0.f) ? 127.0f / m : 0.f;
    int8_t q[8];
    q[0] = q8(a.x, inv); q[1] = q8(a.y, inv); q[2] = q8(a.z, inv); q[3] = q8(a.w, inv);
    q[4] = q8(b.x, inv); q[5] = q8(b.y, inv); q[6] = q8(b.z, inv); q[7] = q8(b.w, inv);
    *reinterpret_cast<uint2*>(g_E8 + (size_t)k * D_DIM + lane * 8) = *reinterpret_cast<uint2*>(q);
    if (lane == 0) g_ec[k] = make_float2(s + 2048.0f, 2.0f * m / 127.0f);
    if (threadIdx.x < 8) g_counts[blockIdx.x * 8 + threadIdx.x] = 0;
}

// ---------------- kernel 2: quantize Z ----------------
__global__ void quant_z_kernel(const float* __restrict__ Z) {
    int warp = threadIdx.x >> 5, lane = threadIdx.x & 31;
    int n = blockIdx.x * 8 + warp;
    const float* row = Z + (size_t)n * D_DIM;
    float4 a = *reinterpret_cast<const float4*>(row + lane * 8);
    float4 b = *reinterpret_cast<const float4*>(row + lane * 8 + 4);
    float m = fmaxf(fmaxf(fmaxf(fabsf(a.x), fabsf(a.y)), fmaxf(fabsf(a.z), fabsf(a.w))),
                    fmaxf(fmaxf(fabsf(b.x), fabsf(b.y)), fmaxf(fabsf(b.z), fabsf(b.w))));
#pragma unroll
    for (int o = 16; o > 0; o >>= 1) m = fmaxf(m, __shfl_xor_sync(0xffffffffu, m, o));
    float inv = (m > 0.f) ? 127.0f / m : 0.f;
    int8_t q[8];
    q[0] = q8(a.x, inv); q[1] = q8(a.y, inv); q[2] = q8(a.z, inv); q[3] = q8(a.w, inv);
    q[4] = q8(b.x, inv); q[5] = q8(b.y, inv); q[6] = q8(b.z, inv); q[7] = q8(b.w, inv);
    *reinterpret_cast<uint2*>(g_Z8 + (size_t)n * D_DIM + lane * 8) = *reinterpret_cast<uint2*>(q);
    if (lane == 0) g_zs[n] = m / 127.0f;
}

__global__ void dummy_kernel() {}

// ---------------- kernel 3: int8 IMMA GEMM + fused top-4 ----------------
static __device__ __forceinline__ void load_tile_i8(uint32_t dst, const int8_t* gsrc, int tid) {
#pragma unroll
    for (int i = 0; i < 8; i++) {
        int c = tid + i * 256;                // 16B chunks, 0..2047
        int row = c >> 4, ch = c & 15;
        uint32_t sa = dst + row * 256 + (uint32_t)((ch ^ (row & 7)) << 4);
        cpasync16(sa, gsrc + row * 256 + ch * 16);
    }
}

__global__ __launch_bounds__(256, 2)
void approx_kernel() {
    extern __shared__ char smem[];
    const uint32_t sb = smem_u32(smem);
    const int tid = threadIdx.x;
    const int lane = tid & 31;
    const int wid = tid >> 5;
    const int wm = wid & 3;
    const int wn = wid >> 2;
    const int m0 = blockIdx.x * 128;

    // prologue: A tile + B0 (group0), B1 (group1)
    load_tile_i8(sb + SM_A, g_Z8 + (size_t)m0 * D_DIM, tid);
    load_tile_i8(sb + SM_B0, g_E8, tid);
    asm volatile("cp.async.commit_group;" ::: "memory");
    load_tile_i8(sb + SM_B1, g_E8 + 128 * D_DIM, tid);
    asm volatile("cp.async.commit_group;" ::: "memory");

    // per-slot token scales: slot s -> row wm*32 + (s>>1)*16 + (s&1)*8 + (lane>>2)
    float sz[4];
#pragma unroll
    for (int s = 0; s < 4; s++)
        sz[s] = g_zs[m0 + wm * 32 + (s >> 1) * 16 + (s & 1) * 8 + (lane >> 2)];

    uint32_t tv0 = 0xFFFFFFFFu, tv1 = 0xFFFFFFFFu, tv2 = 0xFFFFFFFFu, tv3 = 0xFFFFFFFFu;
    // per-slot lists kept as 4 independent sets via arrays
    uint32_t T[4][4];
#pragma unroll
    for (int s = 0; s < 4; s++) { T[s][0] = T[s][1] = T[s][2] = T[s][3] = 0xFFFFFFFFu; }
    (void)tv0; (void)tv1; (void)tv2; (void)tv3;

    for (int nt = 0; nt < 32; nt++) {
        if (nt < 31) asm volatile("cp.async.wait_group 1;" ::: "memory");
        else         asm volatile("cp.async.wait_group 0;" ::: "memory");
        __syncthreads();
        const uint32_t Bb = sb + ((nt & 1) ? SM_B1 : SM_B0);

        int acc[2][8][4];
#pragma unroll
        for (int mi = 0; mi < 2; mi++)
#pragma unroll
            for (int nj = 0; nj < 8; nj++)
#pragma unroll
                for (int r = 0; r < 4; r++) acc[mi][nj][r] = 0;

#pragma unroll
        for (int ks = 0; ks < 8; ks++) {
            uint32_t a[2][4], b[4][4];
#pragma unroll
            for (int mi = 0; mi < 2; mi++) {
                int ar = wm * 32 + mi * 16 + (lane & 15);
                int ch = ks * 2 + (lane >> 4);
                ldsm4(a[mi], sb + SM_A + ar * 256 + ((ch ^ (ar & 7)) << 4));
            }
#pragma unroll
            for (int g = 0; g < 4; g++) {
                int br = wn * 64 + g * 16 + (lane & 7) + ((lane >> 4) & 1) * 8;
                int ch = ks * 2 + ((lane >> 3) & 1);
                ldsm4(b[g], Bb + br * 256 + ((ch ^ (br & 7)) << 4));
            }
#pragma unroll
            for (int mi = 0; mi < 2; mi++)
#pragma unroll
                for (int g = 0; g < 4; g++) {
                    imma16832(acc[mi][2 * g],     a[mi], b[g][0], b[g][1]);
                    imma16832(acc[mi][2 * g + 1], a[mi], b[g][2], b[g][3]);
                }
        }

        // epilogue: key = bits(esqp - sz*cs*I) masked | code
        const int n0 = nt * 128 + wn * 64;
#pragma unroll
        for (int nj = 0; nj < 8; nj++) {
            int kb = n0 + nj * 8 + (lane & 3) * 2;
            float4 ec = *reinterpret_cast<const float4*>(&g_ec[kb]);  // esqp0,cs0,esqp1,cs1
#pragma unroll
            for (int mi = 0; mi < 2; mi++)
#pragma unroll
                for (int h = 0; h < 2; h++) {
                    int s = mi * 2 + h;
                    float t0 = sz[s] * ec.y;
                    float t1 = sz[s] * ec.w;
                    float v0 = fmaf(-t0, __int2float_rn(acc[mi][nj][h * 2]),     ec.x);
                    float v1 = fmaf(-t1, __int2float_rn(acc[mi][nj][h * 2 + 1]), ec.z);
                    uint32_t k0 = (__float_as_uint(v0) & 0xFFFFF000u) | (uint32_t)kb;
                    uint32_t k1 = (__float_as_uint(v1) & 0xFFFFF000u) | (uint32_t)(kb + 1);
                    ins4u(k0, T[s][0], T[s][1], T[s][2], T[s][3]);
                    ins4u(k1, T[s][0], T[s][1], T[s][2], T[s][3]);
                }
        }
        __syncthreads();
        if (nt + 2 < 32) {
            load_tile_i8(sb + ((nt & 1) ? SM_B1 : SM_B0), g_E8 + (size_t)(nt + 2) * 128 * D_DIM, tid);
            asm volatile("cp.async.commit_group;" ::: "memory");
        }
    }

    // quad merge: lanes l^1, l^2 share token rows
#pragma unroll
    for (int off = 1; off <= 2; off <<= 1) {
#pragma unroll
        for (int s = 0; s < 4; s++) {
            uint32_t o0 = __shfl_xor_sync(0xffffffffu, T[s][0], off);
            uint32_t o1 = __shfl_xor_sync(0xffffffffu, T[s][1], off);
            uint32_t o2 = __shfl_xor_sync(0xffffffffu, T[s][2], off);
            uint32_t o3 = __shfl_xor_sync(0xffffffffu, T[s][3], off);
            ins4u(o0, T[s][0], T[s][1], T[s][2], T[s][3]);
            ins4u(o1, T[s][0], T[s][1], T[s][2], T[s][3]);
            ins4u(o2, T[s][0], T[s][1], T[s][2], T[s][3]);
            ins4u(o3, T[s][0], T[s][1], T[s][2], T[s][3]);
        }
    }

    uint32_t* smk = reinterpret_cast<uint32_t*>(smem + SM_TOP);
    if ((lane & 3) == 0) {
#pragma unroll
        for (int s = 0; s < 4; s++) {
            int r = wm * 32 + (s >> 1) * 16 + (s & 1) * 8 + (lane >> 2);
            uint32_t* dst = smk + (r * 2 + wn) * 4;
            dst[0] = T[s][0]; dst[1] = T[s][1]; dst[2] = T[s][2]; dst[3] = T[s][3];
        }
    }
    __syncthreads();
    if (tid < 128) {
        uint4 A4 = *reinterpret_cast<uint4*>(smk + (tid * 2) * 4);
        uint4 B4 = *reinterpret_cast<uint4*>(smk + (tid * 2 + 1) * 4);
        uint32_t a0 = A4.x, a1 = A4.y, a2 = A4.z, a3 = A4.w;
        ins4u(B4.x, a0, a1, a2, a3);
        ins4u(B4.y, a0, a1, a2, a3);
        ins4u(B4.z, a0, a1, a2, a3);
        ins4u(B4.w, a0, a1, a2, a3);
        *reinterpret_cast<uint4*>(&g_topk[(size_t)(m0 + tid) * 4]) = make_uint4(a0, a1, a2, a3);
    }
}

// ---------------- kernel 4: exact rescore + gather + loss + hist + last-block finalize ----------------
__global__ void rescue_kernel(const float* __restrict__ Z, const float* __restrict__ E,
                              float* __restrict__ zq_out, float* __restrict__ out_idx_f,
                              float* __restrict__ out_scalars, int N, int K) {
    const int warp = threadIdx.x >> 5;
    const int lane = threadIdx.x & 31;
    const int token = blockIdx.x * 8 + warp;

    const float* zr = Z + (size_t)token * D_DIM;
    float4 z0 = *reinterpret_cast<const float4*>(zr + lane * 8);
    float4 z1 = *reinterpret_cast<const float4*>(zr + lane * 8 + 4);

    uint4 tk = *reinterpret_cast<const uint4*>(&g_topk[(size_t)token * 4]);
    int ks[4] = { (int)(tk.x & 4095u), (int)(tk.y & 4095u), (int)(tk.z & 4095u), (int)(tk.w & 4095u) };
    float dots[4];
#pragma unroll
    for (int j = 0; j < 4; j++) {
        const float* er = E + (size_t)ks[j] * D_DIM;
        float4 e0 = *reinterpret_cast<const float4*>(er + lane * 8);
        float4 e1 = *reinterpret_cast<const float4*>(er + lane * 8 + 4);
        dots[j] = z0.x * e0.x + z0.y * e0.y + z0.z * e0.z + z0.w * e0.w
                + z1.x * e1.x + z1.y * e1.y + z1.z * e1.z + z1.w * e1.w;
    }
#pragma unroll
    for (int o = 16; o > 0; o >>= 1)
#pragma unroll
        for (int j = 0; j < 4; j++) dots[j] += __shfl_xor_sync(0xffffffffu, dots[j], o);

    float bv = 3.4e38f; int bk = 0x7FFFFFFF;
#pragma unroll
    for (int j = 0; j < 4; j++) {
        float v = g_ec[ks[j]].x - 2048.0f - 2.0f * dots[j];
        if (v < bv || (v == bv && ks[j] < bk)) { bv = v; bk = ks[j]; }
    }

    const float* er = E + (size_t)bk * D_DIM;
    float* orow = zq_out + (size_t)token * D_DIM;
    float s = 0.f;
#pragma unroll
    for (int h = 0; h < 2; h++) {
        int off = h * 128 + lane * 4;
        float4 ev = *reinterpret_cast<const float4*>(er + off);
        float4 zv = *reinterpret_cast<const float4*>(zr + off);
        float dx = ev.x - zv.x, dy = ev.y - zv.y, dz = ev.z - zv.z, dw = ev.w - zv.w;
        s += dx * dx + dy * dy + dz * dz + dw * dw;
        *reinterpret_cast<float4*>(orow + off) = ev;
    }
    if (lane == 0) {
        atomicAdd(&g_counts[bk], 1);
        out_idx_f[token] = (float)bk;
    }
#pragma unroll
    for (int o = 16; o > 0; o >>= 1) s += __shfl_down_sync(0xffffffffu, s, o);
    __shared__ float sh[8];
    __shared__ int last;
    if (lane == 0) sh[warp] = s;
    __syncthreads();
    if (threadIdx.x == 0) {
        float t = 0.f;
        for (int w = 0; w < 8; w++) t += sh[w];
        g_partials[blockIdx.x] = t;
        __threadfence();
        int ticket = atomicAdd(&g_done, 1);
        last = (ticket == gridDim.x - 1) ? 1 : 0;
    }
    __syncthreads();
    if (!last) return;

    // ---- finalize (single last block, 256 threads) ----
    __shared__ float red[256];
    const int nPart = gridDim.x;
    float acc = 0.f;
    for (int i = threadIdx.x; i < nPart; i += 256) acc += g_partials[i];
    red[threadIdx.x] = acc;
    __syncthreads();
    for (int st = 128; st > 0; st >>= 1) {
        if (threadIdx.x < st) red[threadIdx.x] += red[threadIdx.x + st];
        __syncthreads();
    }
    float loss = 0.1f * red[0] / (float)((size_t)N * D_DIM);
    __syncthreads();
    float e = 0.f;
    for (int i = threadIdx.x; i < K; i += 256) {
        float p = (float)g_counts[i] / (float)N;
        e += p * logf(p + 1e-10f);
    }
    red[threadIdx.x] = e;
    __syncthreads();
    for (int st = 128; st > 0; st >>= 1) {
        if (threadIdx.x < st) red[threadIdx.x] += red[threadIdx.x + st];
        __syncthreads();
    }
    if (threadIdx.x == 0) {
        out_scalars[0] = loss;
        out_scalars[1] = expf(-red[0]);
        g_done = 0;   // reset for next graph replay
    }
}

extern "C" void kernel_launch(void* const* d_in, const int* in_sizes, int n_in,
                              void* d_out, int out_size) {
    const float* Z = (const float*)d_in[0];
    const float* E = (const float*)d_in[1];
    int N = in_sizes[0] / D_DIM;
    int K = in_sizes[1] / D_DIM;

    float* out  = (float*)d_out;
    float* zq   = out;
    float* idxf = out + (size_t)N * D_DIM;
    float* scal = idxf + N;

    cudaFuncSetAttribute(approx_kernel, cudaFuncAttributeMaxDynamicSharedMemorySize, SMEM_TOTAL);

    prep_e_kernel<<<K / 8, 256>>>(E);
    quant_z_kernel<<<N / 8, 256>>>(Z);
    dummy_kernel<<<1, 32>>>();
    approx_kernel<<<N / 128, 256, SMEM_TOTAL>>>();
    rescue_kernel<<<N / 8, 256>>>(Z, E, zq, idxf, scal, N, K);
}

// round 5
// speedup vs baseline: 6.2191x; 2.1886x over previous
#include <cuda_runtime.h>
#include <cuda_fp16.h>
#include <cstdint>

#define D_DIM 256
#define NTOK  65536
#define KCODE 4096

// ---------------- scratch globals ----------------
__device__ float  g_esqp[KCODE];        // esq + 2048
__device__ int    g_counts[KCODE];
__device__ float  g_partials[NTOK / 8];
__device__ __align__(16) __half g_Eh[KCODE * D_DIM];
__device__ __align__(16) __half g_Zh[NTOK * D_DIM];
__device__ __align__(16) uint32_t g_topk[NTOK * 4];
__device__ int    g_done;

// SMEM: A 64KB | B0 64KB | B1 64KB | tops 4KB
#define SM_A    0
#define SM_B0   65536
#define SM_B1   131072
#define SM_TOP  196608
#define SMEM_TOTAL 200704

static __device__ __forceinline__ uint32_t smem_u32(const void* p) {
    uint32_t a;
    asm("{ .reg .u64 t; cvta.to.shared.u64 t, %1; cvt.u32.u64 %0, t; }" : "=r"(a) : "l"(p));
    return a;
}
static __device__ __forceinline__ void ldsm4(uint32_t* r, uint32_t addr) {
    asm volatile("ldmatrix.sync.aligned.m8n8.x4.shared.b16 {%0,%1,%2,%3}, [%4];"
                 : "=r"(r[0]), "=r"(r[1]), "=r"(r[2]), "=r"(r[3]) : "r"(addr));
}
// fp16 x fp16 -> fp16 accumulate (half-rate-accumulator hypothesis test)
static __device__ __forceinline__ void hmma16816_f16(uint32_t& c0, uint32_t& c1,
                                                     const uint32_t* a, uint32_t b0, uint32_t b1) {
    asm volatile("mma.sync.aligned.m16n8k16.row.col.f16.f16.f16.f16 "
                 "{%0,%1}, {%2,%3,%4,%5}, {%6,%7}, {%0,%1};"
                 : "+r"(c0), "+r"(c1)
                 : "r"(a[0]), "r"(a[1]), "r"(a[2]), "r"(a[3]), "r"(b0), "r"(b1));
}
static __device__ __forceinline__ void cpasync16(uint32_t sa, const void* ga) {
    asm volatile("cp.async.cg.shared.global [%0], [%1], 16;" :: "r"(sa), "l"(ga));
}
// branchless ordered insert of key into ascending 4-list
static __device__ __forceinline__ void ins4u(uint32_t k, uint32_t& t0, uint32_t& t1,
                                             uint32_t& t2, uint32_t& t3) {
    if (k < t3) {
        uint32_t m2 = min(t2, k);  t3 = max(t2, k);
        uint32_t m1 = min(t1, m2); t2 = max(t1, m2);
        uint32_t m0 = min(t0, m1); t1 = max(t0, m1); t0 = m0;
    }
}

// ---------------- kernel 1: prep E (esq+2048, fp16 copy, zero counts) ----------------
__global__ void prep_e_kernel(const float* __restrict__ E) {
    int warp = threadIdx.x >> 5, lane = threadIdx.x & 31;
    int k = blockIdx.x * 8 + warp;
    const float* row = E + (size_t)k * D_DIM;
    float4 a = *reinterpret_cast<const float4*>(row + lane * 8);
    float4 b = *reinterpret_cast<const float4*>(row + lane * 8 + 4);
    float s = a.x * a.x + a.y * a.y + a.z * a.z + a.w * a.w
            + b.x * b.x + b.y * b.y + b.z * b.z + b.w * b.w;
#pragma unroll
    for (int o = 16; o > 0; o >>= 1) s += __shfl_xor_sync(0xffffffffu, s, o);
    __half h[8];
    h[0] = __float2half_rn(a.x); h[1] = __float2half_rn(a.y);
    h[2] = __float2half_rn(a.z); h[3] = __float2half_rn(a.w);
    h[4] = __float2half_rn(b.x); h[5] = __float2half_rn(b.y);
    h[6] = __float2half_rn(b.z); h[7] = __float2half_rn(b.w);
    *reinterpret_cast<uint4*>(g_Eh + (size_t)k * D_DIM + lane * 8) = *reinterpret_cast<uint4*>(h);
    if (lane == 0) g_esqp[k] = s + 2048.0f;
    if (blockIdx.x < 16) g_counts[blockIdx.x * 256 + threadIdx.x] = 0;
}

// ---------------- kernel 2: Z -> fp16 ----------------
__global__ void quant_z_kernel(const float* __restrict__ Z) {
    int warp = threadIdx.x >> 5, lane = threadIdx.x & 31;
    int n = blockIdx.x * 8 + warp;
    const float* row = Z + (size_t)n * D_DIM;
    float4 a = *reinterpret_cast<const float4*>(row + lane * 8);
    float4 b = *reinterpret_cast<const float4*>(row + lane * 8 + 4);
    __half h[8];
    h[0] = __float2half_rn(a.x); h[1] = __float2half_rn(a.y);
    h[2] = __float2half_rn(a.z); h[3] = __float2half_rn(a.w);
    h[4] = __float2half_rn(b.x); h[5] = __float2half_rn(b.y);
    h[6] = __float2half_rn(b.z); h[7] = __float2half_rn(b.w);
    *reinterpret_cast<uint4*>(g_Zh + (size_t)n * D_DIM + lane * 8) = *reinterpret_cast<uint4*>(h);
}

__global__ void dummy_kernel() {}

// ---------------- kernel 3: fp16-accum HMMA GEMM + fused top-4 ----------------
static __device__ __forceinline__ void load_tile_f16(uint32_t dst, const __half* gsrc, int tid) {
    const char* gbase = (const char*)gsrc;
#pragma unroll
    for (int i = 0; i < 16; i++) {
        int c = tid + i * 256;                // 16B chunks, 0..4095
        int row = c >> 5, ch = c & 31;
        uint32_t sa = dst + row * 512 + (uint32_t)((ch ^ (row & 7)) << 4);
        cpasync16(sa, gbase + row * 512 + ch * 16);
    }
}

__global__ __launch_bounds__(256, 1)
void approx_kernel() {
    extern __shared__ char smem[];
    const uint32_t sb = smem_u32(smem);
    const int tid = threadIdx.x;
    const int lane = tid & 31;
    const int wid = tid >> 5;
    const int wm = wid & 3;      // M warp (rows wm*32)
    const int wn = wid >> 2;     // N warp (cols wn*64)
    const int m0 = blockIdx.x * 128;

    // prologue: A tile + B0, B1
    load_tile_f16(sb + SM_A, g_Zh + (size_t)m0 * D_DIM, tid);
    load_tile_f16(sb + SM_B0, g_Eh, tid);
    asm volatile("cp.async.commit_group;" ::: "memory");
    load_tile_f16(sb + SM_B1, g_Eh + 128 * D_DIM, tid);
    asm volatile("cp.async.commit_group;" ::: "memory");

    uint32_t T[4][4];
#pragma unroll
    for (int s = 0; s < 4; s++) { T[s][0] = T[s][1] = T[s][2] = T[s][3] = 0xFFFFFFFFu; }

    for (int nt = 0; nt < 32; nt++) {
        if (nt < 31) asm volatile("cp.async.wait_group 1;" ::: "memory");
        else         asm volatile("cp.async.wait_group 0;" ::: "memory");
        __syncthreads();
        const uint32_t Bb = sb + ((nt & 1) ? SM_B1 : SM_B0);

        uint32_t acc[2][8][2];
#pragma unroll
        for (int mi = 0; mi < 2; mi++)
#pragma unroll
            for (int nj = 0; nj < 8; nj++) { acc[mi][nj][0] = 0u; acc[mi][nj][1] = 0u; }

#pragma unroll
        for (int ks = 0; ks < 16; ks++) {
            uint32_t a[2][4], b[4][4];
#pragma unroll
            for (int mi = 0; mi < 2; mi++) {
                int ar = wm * 32 + mi * 16 + (lane & 15);
                int ch = ks * 2 + (lane >> 4);
                ldsm4(a[mi], sb + SM_A + ar * 512 + ((ch ^ (ar & 7)) << 4));
            }
#pragma unroll
            for (int g = 0; g < 4; g++) {
                int br = wn * 64 + g * 16 + (lane & 7) + ((lane >> 4) & 1) * 8;
                int ch = ks * 2 + ((lane >> 3) & 1);
                ldsm4(b[g], Bb + br * 512 + ((ch ^ (br & 7)) << 4));
            }
#pragma unroll
            for (int mi = 0; mi < 2; mi++)
#pragma unroll
                for (int g = 0; g < 4; g++) {
                    hmma16816_f16(acc[mi][2 * g][0],     acc[mi][2 * g][1],     a[mi], b[g][0], b[g][1]);
                    hmma16816_f16(acc[mi][2 * g + 1][0], acc[mi][2 * g + 1][1], a[mi], b[g][2], b[g][3]);
                }
        }

        // epilogue: key = bits(esqp - 2*dot) masked | code
        const int n0 = nt * 128 + wn * 64;
#pragma unroll
        for (int nj = 0; nj < 8; nj++) {
            int kb = n0 + nj * 8 + (lane & 3) * 2;
            float2 ep = *reinterpret_cast<const float2*>(g_esqp + kb);  // esqp0, esqp1
#pragma unroll
            for (int mi = 0; mi < 2; mi++)
#pragma unroll
                for (int h = 0; h < 2; h++) {
                    int s = mi * 2 + h;
                    float2 d = __half22float2(*reinterpret_cast<__half2*>(&acc[mi][nj][h]));
                    float v0 = fmaf(-2.0f, d.x, ep.x);
                    float v1 = fmaf(-2.0f, d.y, ep.y);
                    uint32_t k0 = (__float_as_uint(v0) & 0xFFFFF000u) | (uint32_t)kb;
                    uint32_t k1 = (__float_as_uint(v1) & 0xFFFFF000u) | (uint32_t)(kb + 1);
                    ins4u(k0, T[s][0], T[s][1], T[s][2], T[s][3]);
                    ins4u(k1, T[s][0], T[s][1], T[s][2], T[s][3]);
                }
        }
        __syncthreads();
        if (nt + 2 < 32) {
            load_tile_f16(sb + ((nt & 1) ? SM_B1 : SM_B0), g_Eh + (size_t)(nt + 2) * 128 * D_DIM, tid);
            asm volatile("cp.async.commit_group;" ::: "memory");
        }
    }

    // quad merge: lanes l^1, l^2 share token rows
#pragma unroll
    for (int off = 1; off <= 2; off <<= 1) {
#pragma unroll
        for (int s = 0; s < 4; s++) {
            uint32_t o0 = __shfl_xor_sync(0xffffffffu, T[s][0], off);
            uint32_t o1 = __shfl_xor_sync(0xffffffffu, T[s][1], off);
            uint32_t o2 = __shfl_xor_sync(0xffffffffu, T[s][2], off);
            uint32_t o3 = __shfl_xor_sync(0xffffffffu, T[s][3], off);
            ins4u(o0, T[s][0], T[s][1], T[s][2], T[s][3]);
            ins4u(o1, T[s][0], T[s][1], T[s][2], T[s][3]);
            ins4u(o2, T[s][0], T[s][1], T[s][2], T[s][3]);
            ins4u(o3, T[s][0], T[s][1], T[s][2], T[s][3]);
        }
    }

    uint32_t* smk = reinterpret_cast<uint32_t*>(smem + SM_TOP);
    if ((lane & 3) == 0) {
#pragma unroll
        for (int s = 0; s < 4; s++) {
            int r = wm * 32 + (s >> 1) * 16 + (s & 1) * 8 + (lane >> 2);
            uint32_t* dst = smk + (r * 2 + wn) * 4;
            dst[0] = T[s][0]; dst[1] = T[s][1]; dst[2] = T[s][2]; dst[3] = T[s][3];
        }
    }
    __syncthreads();
    if (tid < 128) {
        uint4 A4 = *reinterpret_cast<uint4*>(smk + (tid * 2) * 4);
        uint4 B4 = *reinterpret_cast<uint4*>(smk + (tid * 2 + 1) * 4);
        uint32_t a0 = A4.x, a1 = A4.y, a2 = A4.z, a3 = A4.w;
        ins4u(B4.x, a0, a1, a2, a3);
        ins4u(B4.y, a0, a1, a2, a3);
        ins4u(B4.z, a0, a1, a2, a3);
        ins4u(B4.w, a0, a1, a2, a3);
        *reinterpret_cast<uint4*>(&g_topk[(size_t)(m0 + tid) * 4]) = make_uint4(a0, a1, a2, a3);
    }
}

// ---------------- kernel 4: exact rescore + gather + loss + hist + last-block finalize ----------------
__global__ void rescue_kernel(const float* __restrict__ Z, const float* __restrict__ E,
                              float* __restrict__ zq_out, float* __restrict__ out_idx_f,
                              float* __restrict__ out_scalars, int N, int K) {
    const int warp = threadIdx.x >> 5;
    const int lane = threadIdx.x & 31;
    const int token = blockIdx.x * 8 + warp;

    const float* zr = Z + (size_t)token * D_DIM;
    float4 z0 = *reinterpret_cast<const float4*>(zr + lane * 8);
    float4 z1 = *reinterpret_cast<const float4*>(zr + lane * 8 + 4);

    uint4 tk = *reinterpret_cast<const uint4*>(&g_topk[(size_t)token * 4]);
    int ks[4] = { (int)(tk.x & 4095u), (int)(tk.y & 4095u), (int)(tk.z & 4095u), (int)(tk.w & 4095u) };
    float dots[4];
#pragma unroll
    for (int j = 0; j < 4; j++) {
        const float* er = E + (size_t)ks[j] * D_DIM;
        float4 e0 = *reinterpret_cast<const float4*>(er + lane * 8);
        float4 e1 = *reinterpret_cast<const float4*>(er + lane * 8 + 4);
        dots[j] = z0.x * e0.x + z0.y * e0.y + z0.z * e0.z + z0.w * e0.w
                + z1.x * e1.x + z1.y * e1.y + z1.z * e1.z + z1.w * e1.w;
    }
#pragma unroll
    for (int o = 16; o > 0; o >>= 1)
#pragma unroll
        for (int j = 0; j < 4; j++) dots[j] += __shfl_xor_sync(0xffffffffu, dots[j], o);

    float bv = 3.4e38f; int bk = 0x7FFFFFFF;
#pragma unroll
    for (int j = 0; j < 4; j++) {
        float v = g_esqp[ks[j]] - 2048.0f - 2.0f * dots[j];
        if (v < bv || (v == bv && ks[j] < bk)) { bv = v; bk = ks[j]; }
    }

    const float* er = E + (size_t)bk * D_DIM;
    float* orow = zq_out + (size_t)token * D_DIM;
    float s = 0.f;
#pragma unroll
    for (int h = 0; h < 2; h++) {
        int off = h * 128 + lane * 4;
        float4 ev = *reinterpret_cast<const float4*>(er + off);
        float4 zv = *reinterpret_cast<const float4*>(zr + off);
        float dx = ev.x - zv.x, dy = ev.y - zv.y, dz = ev.z - zv.z, dw = ev.w - zv.w;
        s += dx * dx + dy * dy + dz * dz + dw * dw;
        *reinterpret_cast<float4*>(orow + off) = ev;
    }
    if (lane == 0) {
        atomicAdd(&g_counts[bk], 1);
        out_idx_f[token] = (float)bk;
    }
#pragma unroll
    for (int o = 16; o > 0; o >>= 1) s += __shfl_down_sync(0xffffffffu, s, o);
    __shared__ float sh[8];
    __shared__ int last;
    if (lane == 0) sh[warp] = s;
    __syncthreads();
    if (threadIdx.x == 0) {
        float t = 0.f;
        for (int w = 0; w < 8; w++) t += sh[w];
        g_partials[blockIdx.x] = t;
        __threadfence();
        int ticket = atomicAdd(&g_done, 1);
        last = (ticket == gridDim.x - 1) ? 1 : 0;
    }
    __syncthreads();
    if (!last) return;

    // ---- finalize (single last block) ----
    __shared__ float red[256];
    const int nPart = gridDim.x;
    float acc = 0.f;
    for (int i = threadIdx.x; i < nPart; i += 256) acc += g_partials[i];
    red[threadIdx.x] = acc;
    __syncthreads();
    for (int st = 128; st > 0; st >>= 1) {
        if (threadIdx.x < st) red[threadIdx.x] += red[threadIdx.x + st];
        __syncthreads();
    }
    float loss = 0.1f * red[0] / (float)((size_t)N * D_DIM);
    __syncthreads();
    float e = 0.f;
    for (int i = threadIdx.x; i < K; i += 256) {
        float p = (float)g_counts[i] / (float)N;
        e += p * logf(p + 1e-10f);
    }
    red[threadIdx.x] = e;
    __syncthreads();
    for (int st = 128; st > 0; st >>= 1) {
        if (threadIdx.x < st) red[threadIdx.x] += red[threadIdx.x + st];
        __syncthreads();
    }
    if (threadIdx.x == 0) {
        out_scalars[0] = loss;
        out_scalars[1] = expf(-red[0]);
        g_done = 0;   // reset for next graph replay
    }
}

extern "C" void kernel_launch(void* const* d_in, const int* in_sizes, int n_in,
                              void* d_out, int out_size) {
    const float* Z = (const float*)d_in[0];
    const float* E = (const float*)d_in[1];
    int N = in_sizes[0] / D_DIM;
    int K = in_sizes[1] / D_DIM;

    float* out  = (float*)d_out;
    float* zq   = out;
    float* idxf = out + (size_t)N * D_DIM;
    float* scal = idxf + N;

    cudaFuncSetAttribute(approx_kernel, cudaFuncAttributeMaxDynamicSharedMemorySize, SMEM_TOTAL);

    prep_e_kernel<<<K / 8, 256>>>(E);
    quant_z_kernel<<<N / 8, 256>>>(Z);
    dummy_kernel<<<1, 32>>>();
    approx_kernel<<<N / 128, 256, SMEM_TOTAL>>>();
    rescue_kernel<<<N / 8, 256>>>(Z, E, zq, idxf, scal, N, K);
}

// round 7
// speedup vs baseline: 6.5552x; 1.0540x over previous
#include <cuda_runtime.h>
#include <cuda_fp16.h>
#include <cstdint>

#define D_DIM 256
#define NTOK  65536
#define KCODE 4096

// ---------------- scratch globals ----------------
__device__ float  g_esqp[KCODE];        // esq + 2048 (fp32)
__device__ int    g_counts[KCODE];
__device__ float  g_partials[NTOK / 8];
__device__ __align__(16) __half g_Eh[KCODE * D_DIM];
__device__ __align__(16) __half g_Zh[NTOK * D_DIM];
__device__ __align__(16) uint32_t g_topk[NTOK * 4];
__device__ int    g_done;

// SMEM: A 64KB | B0 64KB | B1 64KB | tops 4KB
#define SM_A    0
#define SM_B0   65536
#define SM_B1   131072
#define SM_TOP  196608
#define SMEM_TOTAL 200704

static __device__ __forceinline__ uint32_t smem_u32(const void* p) {
    uint32_t a;
    asm("{ .reg .u64 t; cvta.to.shared.u64 t, %1; cvt.u32.u64 %0, t; }" : "=r"(a) : "l"(p));
    return a;
}
static __device__ __forceinline__ void ldsm4(uint32_t* r, uint32_t addr) {
    asm volatile("ldmatrix.sync.aligned.m8n8.x4.shared.b16 {%0,%1,%2,%3}, [%4];"
                 : "=r"(r[0]), "=r"(r[1]), "=r"(r[2]), "=r"(r[3]) : "r"(addr));
}
static __device__ __forceinline__ void hmma16816_f16(uint32_t& c0, uint32_t& c1,
                                                     const uint32_t* a, uint32_t b0, uint32_t b1) {
    asm volatile("mma.sync.aligned.m16n8k16.row.col.f16.f16.f16.f16 "
                 "{%0,%1}, {%2,%3,%4,%5}, {%6,%7}, {%0,%1};"
                 : "+r"(c0), "+r"(c1)
                 : "r"(a[0]), "r"(a[1]), "r"(a[2]), "r"(a[3]), "r"(b0), "r"(b1));
}
static __device__ __forceinline__ void cpasync16(uint32_t sa, const void* ga) {
    asm volatile("cp.async.cg.shared.global [%0], [%1], 16;" :: "r"(sa), "l"(ga));
}
static __device__ __forceinline__ void ins4u(uint32_t k, uint32_t& t0, uint32_t& t1,
                                             uint32_t& t2, uint32_t& t3) {
    if (k < t3) {
        uint32_t m2 = min(t2, k);  t3 = max(t2, k);
        uint32_t m1 = min(t1, m2); t2 = max(t1, m2);
        uint32_t m0 = min(t0, m1); t1 = max(t0, m1); t0 = m0;
    }
}

// ---------------- kernel 1: prep E ----------------
__global__ void prep_e_kernel(const float* __restrict__ E) {
    int warp = threadIdx.x >> 5, lane = threadIdx.x & 31;
    int k = blockIdx.x * 8 + warp;
    const float* row = E + (size_t)k * D_DIM;
    float4 a = *reinterpret_cast<const float4*>(row + lane * 8);
    float4 b = *reinterpret_cast<const float4*>(row + lane * 8 + 4);
    float s = a.x * a.x + a.y * a.y + a.z * a.z + a.w * a.w
            + b.x * b.x + b.y * b.y + b.z * b.z + b.w * b.w;
#pragma unroll
    for (int o = 16; o > 0; o >>= 1) s += __shfl_xor_sync(0xffffffffu, s, o);
    __half h[8];
    h[0] = __float2half_rn(a.x); h[1] = __float2half_rn(a.y);
    h[2] = __float2half_rn(a.z); h[3] = __float2half_rn(a.w);
    h[4] = __float2half_rn(b.x); h[5] = __float2half_rn(b.y);
    h[6] = __float2half_rn(b.z); h[7] = __float2half_rn(b.w);
    *reinterpret_cast<uint4*>(g_Eh + (size_t)k * D_DIM + lane * 8) = *reinterpret_cast<uint4*>(h);
    if (lane == 0) g_esqp[k] = s + 2048.0f;
    if (blockIdx.x < 16) g_counts[blockIdx.x * 256 + threadIdx.x] = 0;
}

// ---------------- kernel 2: Z -> fp16 ----------------
__global__ void quant_z_kernel(const float* __restrict__ Z) {
    int warp = threadIdx.x >> 5, lane = threadIdx.x & 31;
    int n = blockIdx.x * 8 + warp;
    const float* row = Z + (size_t)n * D_DIM;
    float4 a = *reinterpret_cast<const float4*>(row + lane * 8);
    float4 b = *reinterpret_cast<const float4*>(row + lane * 8 + 4);
    __half h[8];
    h[0] = __float2half_rn(a.x); h[1] = __float2half_rn(a.y);
    h[2] = __float2half_rn(a.z); h[3] = __float2half_rn(a.w);
    h[4] = __float2half_rn(b.x); h[5] = __float2half_rn(b.y);
    h[6] = __float2half_rn(b.z); h[7] = __float2half_rn(b.w);
    *reinterpret_cast<uint4*>(g_Zh + (size_t)n * D_DIM + lane * 8) = *reinterpret_cast<uint4*>(h);
}

__global__ void dummy_kernel() {}

// ---------------- kernel 3: pipelined fp16-accum HMMA GEMM + interleaved top-4 ----------------
static __device__ __forceinline__ void load_tile_f16(uint32_t dst, const __half* gsrc, int tid) {
    const char* gbase = (const char*)gsrc;
#pragma unroll
    for (int i = 0; i < 16; i++) {
        int c = tid + i * 256;
        int row = c >> 5, ch = c & 31;
        uint32_t sa = dst + row * 512 + (uint32_t)((ch ^ (row & 7)) << 4);
        cpasync16(sa, gbase + row * 512 + ch * 16);
    }
}

// one tile: MMAs into cur[], interleaved epilogue of prev[] (tile nt-1), fp32-masked keys
static __device__ __forceinline__ void tile_body(
    int nt, bool hasPrev, uint32_t sb, int tid, int lane, int wm, int wn,
    uint32_t cur[2][8][2], uint32_t prev[2][8][2], uint32_t T[4][4])
{
    if (nt < 31) asm volatile("cp.async.wait_group 1;" ::: "memory");
    else         asm volatile("cp.async.wait_group 0;" ::: "memory");
    __syncthreads();
    const uint32_t Bb = sb + ((nt & 1) ? SM_B1 : SM_B0);

    // preload fp32 esq pairs for the PREVIOUS tile's epilogue
    float2 e2[8];
    const int kbase = (nt - 1) * 128 + wn * 64 + (lane & 3) * 2;
    if (hasPrev) {
#pragma unroll
        for (int nj = 0; nj < 8; nj++)
            e2[nj] = *reinterpret_cast<const float2*>(g_esqp + kbase + nj * 8);
    }

#pragma unroll
    for (int mi = 0; mi < 2; mi++)
#pragma unroll
        for (int nj = 0; nj < 8; nj++) { cur[mi][nj][0] = 0u; cur[mi][nj][1] = 0u; }

#pragma unroll
    for (int ks = 0; ks < 16; ks++) {
        uint32_t a[2][4], b[4][4];
#pragma unroll
        for (int mi = 0; mi < 2; mi++) {
            int ar = wm * 32 + mi * 16 + (lane & 15);
            int ch = ks * 2 + (lane >> 4);
            ldsm4(a[mi], sb + SM_A + ar * 512 + ((ch ^ (ar & 7)) << 4));
        }
#pragma unroll
        for (int g = 0; g < 4; g++) {
            int br = wn * 64 + g * 16 + (lane & 7) + ((lane >> 4) & 1) * 8;
            int ch = ks * 2 + ((lane >> 3) & 1);
            ldsm4(b[g], Bb + br * 512 + ((ch ^ (br & 7)) << 4));
        }
#pragma unroll
        for (int mi = 0; mi < 2; mi++)
#pragma unroll
            for (int g = 0; g < 4; g++) {
                hmma16816_f16(cur[mi][2 * g][0],     cur[mi][2 * g][1],     a[mi], b[g][0], b[g][1]);
                hmma16816_f16(cur[mi][2 * g + 1][0], cur[mi][2 * g + 1][1], a[mi], b[g][2], b[g][3]);
            }

        // interleaved epilogue chunk of tile nt-1: (nj = ks>>1, mi = ks&1, h = 0..1)
        if (hasPrev) {
            const int nj = ks >> 1;
            const int mi = ks & 1;
            const int kb = kbase + nj * 8;
#pragma unroll
            for (int h = 0; h < 2; h++) {
                const int s = mi * 2 + h;
                float2 d = __half22float2(*reinterpret_cast<__half2*>(&prev[mi][nj][h]));
                float v0 = fmaf(-2.0f, d.x, e2[nj].x);
                float v1 = fmaf(-2.0f, d.y, e2[nj].y);
                uint32_t k0 = (__float_as_uint(v0) & 0xFFFFF000u) | (uint32_t)kb;
                uint32_t k1 = (__float_as_uint(v1) & 0xFFFFF000u) | (uint32_t)(kb + 1);
                ins4u(k0, T[s][0], T[s][1], T[s][2], T[s][3]);
                ins4u(k1, T[s][0], T[s][1], T[s][2], T[s][3]);
            }
        }
    }
    __syncthreads();
    if (nt + 2 < 32) {
        load_tile_f16(sb + ((nt & 1) ? SM_B1 : SM_B0), g_Eh + (size_t)(nt + 2) * 128 * D_DIM, tid);
        asm volatile("cp.async.commit_group;" ::: "memory");
    }
}

// final epilogue for the last tile (nt = 31)
static __device__ __forceinline__ void tail_epilogue(
    int lane, int wn, uint32_t prev[2][8][2], uint32_t T[4][4])
{
    const int kbase = 31 * 128 + wn * 64 + (lane & 3) * 2;
#pragma unroll
    for (int nj = 0; nj < 8; nj++) {
        const int kb = kbase + nj * 8;
        float2 e2 = *reinterpret_cast<const float2*>(g_esqp + kb);
#pragma unroll
        for (int mi = 0; mi < 2; mi++)
#pragma unroll
            for (int h = 0; h < 2; h++) {
                const int s = mi * 2 + h;
                float2 d = __half22float2(*reinterpret_cast<__half2*>(&prev[mi][nj][h]));
                float v0 = fmaf(-2.0f, d.x, e2.x);
                float v1 = fmaf(-2.0f, d.y, e2.y);
                uint32_t k0 = (__float_as_uint(v0) & 0xFFFFF000u) | (uint32_t)kb;
                uint32_t k1 = (__float_as_uint(v1) & 0xFFFFF000u) | (uint32_t)(kb + 1);
                ins4u(k0, T[s][0], T[s][1], T[s][2], T[s][3]);
                ins4u(k1, T[s][0], T[s][1], T[s][2], T[s][3]);
            }
    }
}

__global__ __launch_bounds__(256, 1)
void approx_kernel() {
    extern __shared__ char smem[];
    const uint32_t sb = smem_u32(smem);
    const int tid = threadIdx.x;
    const int lane = tid & 31;
    const int wid = tid >> 5;
    const int wm = wid & 3;
    const int wn = wid >> 2;
    const int m0 = blockIdx.x * 128;

    load_tile_f16(sb + SM_A, g_Zh + (size_t)m0 * D_DIM, tid);
    load_tile_f16(sb + SM_B0, g_Eh, tid);
    asm volatile("cp.async.commit_group;" ::: "memory");
    load_tile_f16(sb + SM_B1, g_Eh + 128 * D_DIM, tid);
    asm volatile("cp.async.commit_group;" ::: "memory");

    uint32_t T[4][4];
#pragma unroll
    for (int s = 0; s < 4; s++) { T[s][0] = T[s][1] = T[s][2] = T[s][3] = 0xFFFFFFFFu; }

    uint32_t accA[2][8][2], accB[2][8][2];

#pragma unroll 1
    for (int p = 0; p < 16; p++) {
        tile_body(2 * p,     (p > 0), sb, tid, lane, wm, wn, accA, accB, T);
        tile_body(2 * p + 1, true,    sb, tid, lane, wm, wn, accB, accA, T);
    }
    tail_epilogue(lane, wn, accB, T);

    // quad merge: lanes l^1, l^2 share token rows
#pragma unroll
    for (int off = 1; off <= 2; off <<= 1) {
#pragma unroll
        for (int s = 0; s < 4; s++) {
            uint32_t o0 = __shfl_xor_sync(0xffffffffu, T[s][0], off);
            uint32_t o1 = __shfl_xor_sync(0xffffffffu, T[s][1], off);
            uint32_t o2 = __shfl_xor_sync(0xffffffffu, T[s][2], off);
            uint32_t o3 = __shfl_xor_sync(0xffffffffu, T[s][3], off);
            ins4u(o0, T[s][0], T[s][1], T[s][2], T[s][3]);
            ins4u(o1, T[s][0], T[s][1], T[s][2], T[s][3]);
            ins4u(o2, T[s][0], T[s][1], T[s][2], T[s][3]);
            ins4u(o3, T[s][0], T[s][1], T[s][2], T[s][3]);
        }
    }

    uint32_t* smk = reinterpret_cast<uint32_t*>(smem + SM_TOP);
    if ((lane & 3) == 0) {
#pragma unroll
        for (int s = 0; s < 4; s++) {
            int r = wm * 32 + (s >> 1) * 16 + (s & 1) * 8 + (lane >> 2);
            uint32_t* dst = smk + (r * 2 + wn) * 4;
            dst[0] = T[s][0]; dst[1] = T[s][1]; dst[2] = T[s][2]; dst[3] = T[s][3];
        }
    }
    __syncthreads();
    if (tid < 128) {
        uint4 A4 = *reinterpret_cast<uint4*>(smk + (tid * 2) * 4);
        uint4 B4 = *reinterpret_cast<uint4*>(smk + (tid * 2 + 1) * 4);
        uint32_t a0 = A4.x, a1 = A4.y, a2 = A4.z, a3 = A4.w;
        ins4u(B4.x, a0, a1, a2, a3);
        ins4u(B4.y, a0, a1, a2, a3);
        ins4u(B4.z, a0, a1, a2, a3);
        ins4u(B4.w, a0, a1, a2, a3);
        *reinterpret_cast<uint4*>(&g_topk[(size_t)(m0 + tid) * 4]) = make_uint4(a0, a1, a2, a3);
    }
}

// ---------------- kernel 4: exact rescore + gather + loss + hist + finalize ----------------
__global__ void rescue_kernel(const float* __restrict__ Z, const float* __restrict__ E,
                              float* __restrict__ zq_out, float* __restrict__ out_idx_f,
                              float* __restrict__ out_scalars, int N, int K) {
    const int warp = threadIdx.x >> 5;
    const int lane = threadIdx.x & 31;
    const int token = blockIdx.x * 8 + warp;

    const float* zr = Z + (size_t)token * D_DIM;
    float4 z0 = *reinterpret_cast<const float4*>(zr + lane * 8);
    float4 z1 = *reinterpret_cast<const float4*>(zr + lane * 8 + 4);

    uint4 tk = *reinterpret_cast<const uint4*>(&g_topk[(size_t)token * 4]);
    int ks[4] = { (int)(tk.x & 4095u), (int)(tk.y & 4095u), (int)(tk.z & 4095u), (int)(tk.w & 4095u) };
    float dots[4];
#pragma unroll
    for (int j = 0; j < 4; j++) {
        const float* er = E + (size_t)ks[j] * D_DIM;
        float4 e0 = *reinterpret_cast<const float4*>(er + lane * 8);
        float4 e1 = *reinterpret_cast<const float4*>(er + lane * 8 + 4);
        dots[j] = z0.x * e0.x + z0.y * e0.y + z0.z * e0.z + z0.w * e0.w
                + z1.x * e1.x + z1.y * e1.y + z1.z * e1.z + z1.w * e1.w;
    }
#pragma unroll
    for (int o = 16; o > 0; o >>= 1)
#pragma unroll
        for (int j = 0; j < 4; j++) dots[j] += __shfl_xor_sync(0xffffffffu, dots[j], o);

    float bv = 3.4e38f; int bk = 0x7FFFFFFF;
#pragma unroll
    for (int j = 0; j < 4; j++) {
        float v = g_esqp[ks[j]] - 2048.0f - 2.0f * dots[j];
        if (v < bv || (v == bv && ks[j] < bk)) { bv = v; bk = ks[j]; }
    }

    const float* er = E + (size_t)bk * D_DIM;
    float* orow = zq_out + (size_t)token * D_DIM;
    float s = 0.f;
#pragma unroll
    for (int h = 0; h < 2; h++) {
        int off = h * 128 + lane * 4;
        float4 ev = *reinterpret_cast<const float4*>(er + off);
        float4 zv = *reinterpret_cast<const float4*>(zr + off);
        float dx = ev.x - zv.x, dy = ev.y - zv.y, dz = ev.z - zv.z, dw = ev.w - zv.w;
        s += dx * dx + dy * dy + dz * dz + dw * dw;
        *reinterpret_cast<float4*>(orow + off) = ev;
    }
    if (lane == 0) {
        atomicAdd(&g_counts[bk], 1);
        out_idx_f[token] = (float)bk;
    }
#pragma unroll
    for (int o = 16; o > 0; o >>= 1) s += __shfl_down_sync(0xffffffffu, s, o);
    __shared__ float sh[8];
    __shared__ int last;
    if (lane == 0) sh[warp] = s;
    __syncthreads();
    if (threadIdx.x == 0) {
        float t = 0.f;
        for (int w = 0; w < 8; w++) t += sh[w];
        g_partials[blockIdx.x] = t;
        __threadfence();
        int ticket = atomicAdd(&g_done, 1);
        last = (ticket == gridDim.x - 1) ? 1 : 0;
    }
    __syncthreads();
    if (!last) return;

    __shared__ float red[256];
    const int nPart = gridDim.x;
    float acc = 0.f;
    for (int i = threadIdx.x; i < nPart; i += 256) acc += g_partials[i];
    red[threadIdx.x] = acc;
    __syncthreads();
    for (int st = 128; st > 0; st >>= 1) {
        if (threadIdx.x < st) red[threadIdx.x] += red[threadIdx.x + st];
        __syncthreads();
    }
    float loss = 0.1f * red[0] / (float)((size_t)N * D_DIM);
    __syncthreads();
    float e = 0.f;
    for (int i = threadIdx.x; i < K; i += 256) {
        float p = (float)g_counts[i] / (float)N;
        e += p * logf(p + 1e-10f);
    }
    red[threadIdx.x] = e;
    __syncthreads();
    for (int st = 128; st > 0; st >>= 1) {
        if (threadIdx.x < st) red[threadIdx.x] += red[threadIdx.x + st];
        __syncthreads();
    }
    if (threadIdx.x == 0) {
        out_scalars[0] = loss;
        out_scalars[1] = expf(-red[0]);
        g_done = 0;
    }
}

extern "C" void kernel_launch(void* const* d_in, const int* in_sizes, int n_in,
                              void* d_out, int out_size) {
    const float* Z = (const float*)d_in[0];
    const float* E = (const float*)d_in[1];
    int N = in_sizes[0] / D_DIM;
    int K = in_sizes[1] / D_DIM;

    float* out  = (float*)d_out;
    float* zq   = out;
    float* idxf = out + (size_t)N * D_DIM;
    float* scal = idxf + N;

    cudaFuncSetAttribute(approx_kernel, cudaFuncAttributeMaxDynamicSharedMemorySize, SMEM_TOTAL);

    prep_e_kernel<<<K / 8, 256>>>(E);
    quant_z_kernel<<<N / 8, 256>>>(Z);
    dummy_kernel<<<1, 32>>>();
    approx_kernel<<<N / 128, 256, SMEM_TOTAL>>>();
    rescue_kernel<<<N / 8, 256>>>(Z, E, zq, idxf, scal, N, K);
}